// round 11
// baseline (speedup 1.0000x reference)
#include <cuda_runtime.h>
#include <cuda_fp16.h>
#include <math.h>
#include <stdint.h>

#define NE    2048
#define FEAT  512
#define REST  8
#define HEAD  8
#define HL    512
#define NCOL  16384
#define OUTC  (HEAD*512)
#define BKH   64
#define PADH  72
#define ASTRH (128*PADH)
#define STG   3
#define SMEM_BYTES (2 * STG * ASTRH * 2)   // 110592 bytes

// ---------------- scratch ----------------------------------------------------
__device__ __half g_Y  [(size_t)2 * HEAD * NE * 512];
__device__ __half g_Yd [(size_t)HEAD * 512 * NE];
__device__ __half g_xt [(size_t)NCOL * FEAT];
__device__ __half g_W  [(size_t)3 * HL * FEAT];
__device__ __half g_S  [(size_t)HEAD * NE * NE];
__device__ float  g_ss [3 * NE];
__device__ float  g_rs [(size_t)HEAD * NE];

// ---------------- helpers ----------------------------------------------------
__device__ __forceinline__ uint32_t smem_u32(const void* p) {
    uint32_t a;
    asm("{ .reg .u64 t; cvta.to.shared.u64 t, %1; cvt.u32.u64 %0, t; }" : "=r"(a) : "l"(p));
    return a;
}
// fp16-accumulate MMA: D(f16x4) = A*B + C
__device__ __forceinline__ void mma16h_set(uint32_t* d, const uint32_t* a, const uint32_t* b) {
    asm volatile(
        "mma.sync.aligned.m16n8k16.row.col.f16.f16.f16.f16 "
        "{%0,%1}, {%2,%3,%4,%5}, {%6,%7}, {%8,%9};"
        : "=r"(d[0]), "=r"(d[1])
        : "r"(a[0]), "r"(a[1]), "r"(a[2]), "r"(a[3]),
          "r"(b[0]), "r"(b[1]), "r"(0u), "r"(0u));
}
__device__ __forceinline__ void mma16h_acc(uint32_t* d, const uint32_t* a, const uint32_t* b) {
    asm volatile(
        "mma.sync.aligned.m16n8k16.row.col.f16.f16.f16.f16 "
        "{%0,%1}, {%2,%3,%4,%5}, {%6,%7}, {%0,%1};"
        : "+r"(d[0]), "+r"(d[1])
        : "r"(a[0]), "r"(a[1]), "r"(a[2]), "r"(a[3]), "r"(b[0]), "r"(b[1]));
}
__device__ __forceinline__ void ldsm4(uint32_t* r, uint32_t addr) {
    asm volatile("ldmatrix.sync.aligned.m8n8.x4.shared.b16 {%0,%1,%2,%3}, [%4];"
                 : "=r"(r[0]), "=r"(r[1]), "=r"(r[2]), "=r"(r[3]) : "r"(addr));
}
__device__ __forceinline__ void cp16(uint32_t dst, const void* src) {
    uint64_t g;
    asm("cvta.to.global.u64 %0, %1;" : "=l"(g) : "l"(src));
    asm volatile("cp.async.cg.shared.global [%0], [%1], 16;" :: "r"(dst), "l"(g));
}

__device__ __forceinline__ void ld_k(__half* S, const __half* gp, int ldk, int k0, int tid) {
#pragma unroll
    for (int i = 0; i < 8; i++) {
        int idx = tid + i * 128;
        int row = idx >> 3, ch = idx & 7;
        cp16(smem_u32(S + row * PADH + ch * 8), gp + (size_t)row * ldk + k0 + ch * 8);
    }
}

struct Acc { float a[4][8][4]; };

// ------- 3-stage pipeline, fp16 accumulate per 64-K tile, fp32 promote -------
__device__ __forceinline__ void gemm_main(Acc& F, const __half* A, const __half* B,
                                          int K, __half* sA, __half* sB) {
    const int tid = threadIdx.x;
    const int lane = tid & 31, wid = tid >> 5;
    const int wm = (wid & 1) * 64, wn = (wid >> 1) * 64;

    const int offA = (wm + (lane & 7) + ((lane >> 3) & 1) * 8) * PADH + ((lane >> 4) & 1) * 8;
    const int offB = (wn + (lane & 7) + ((lane >> 4) & 1) * 8) * PADH + ((lane >> 3) & 1) * 8;

    const uint32_t sA0 = smem_u32(sA), sB0 = smem_u32(sB);

#pragma unroll
    for (int mt = 0; mt < 4; mt++)
#pragma unroll
        for (int nt = 0; nt < 8; nt++)
#pragma unroll
            for (int j = 0; j < 4; j++) F.a[mt][nt][j] = 0.f;

#pragma unroll
    for (int s = 0; s < STG - 1; s++) {
        ld_k(sA + s * ASTRH, A, K, s * BKH, tid);
        ld_k(sB + s * ASTRH, B, K, s * BKH, tid);
        asm volatile("cp.async.commit_group;" ::: "memory");
    }

    const int KT = K / BKH;
    int ls = STG - 1;
    for (int kt = 0; kt < KT; kt++) {
        asm volatile("cp.async.wait_group %0;" :: "n"(STG - 2) : "memory");
        __syncthreads();
        if (kt + STG - 1 < KT) {
            ld_k(sA + ls * ASTRH, A, K, (kt + STG - 1) * BKH, tid);
            ld_k(sB + ls * ASTRH, B, K, (kt + STG - 1) * BKH, tid);
            ls = (ls + 1 == STG) ? 0 : ls + 1;
        }
        asm volatile("cp.async.commit_group;" ::: "memory");

        int buf = kt % STG;
        const uint32_t aB = sA0 + (buf * ASTRH + offA) * 2;
        const uint32_t bB = sB0 + (buf * ASTRH + offB) * 2;

        uint32_t hacc[4][8][2];
#pragma unroll
        for (int ks = 0; ks < 4; ks++) {
            uint32_t af[4][4], bf[4][4];
#pragma unroll
            for (int mt = 0; mt < 4; mt++) ldsm4(af[mt], aB + (mt * 16 * PADH + 16 * ks) * 2);
#pragma unroll
            for (int np = 0; np < 4; np++) ldsm4(bf[np], bB + (np * 16 * PADH + 16 * ks) * 2);
            if (ks == 0) {
#pragma unroll
                for (int mt = 0; mt < 4; mt++)
#pragma unroll
                    for (int np = 0; np < 4; np++) {
                        mma16h_set(hacc[mt][2 * np + 0], af[mt], &bf[np][0]);
                        mma16h_set(hacc[mt][2 * np + 1], af[mt], &bf[np][2]);
                    }
            } else {
#pragma unroll
                for (int mt = 0; mt < 4; mt++)
#pragma unroll
                    for (int np = 0; np < 4; np++) {
                        mma16h_acc(hacc[mt][2 * np + 0], af[mt], &bf[np][0]);
                        mma16h_acc(hacc[mt][2 * np + 1], af[mt], &bf[np][2]);
                    }
            }
        }
        // promote 64-K fp16 partials into fp32 masters
#pragma unroll
        for (int mt = 0; mt < 4; mt++)
#pragma unroll
            for (int nt = 0; nt < 8; nt++) {
                float2 lo = __half22float2(*(__half2*)&hacc[mt][nt][0]);
                float2 hi = __half22float2(*(__half2*)&hacc[mt][nt][1]);
                F.a[mt][nt][0] += lo.x; F.a[mt][nt][1] += lo.y;
                F.a[mt][nt][2] += hi.x; F.a[mt][nt][3] += hi.y;
            }
    }
    __syncthreads();
}

// ---------------- fused prep: zero accumulators + round W + transpose x ------
__global__ __launch_bounds__(256) void prep_all(const float* __restrict__ x,
                                                const float* __restrict__ Wq,
                                                const float* __restrict__ Wk,
                                                const float* __restrict__ Wd) {
    int b = blockIdx.x;
    if (b < NE) {
        // transpose x -> xt
        __shared__ float s[512 * 9];
        const int n = b, tid = threadIdx.x;
        const float* src = x + (size_t)n * 4096;
#pragma unroll
        for (int i = 0; i < 4; i++) {
            int v = (tid + i * 256) * 4;
            float4 t = *(const float4*)(src + v);
            int f = v >> 3, rr = v & 7;
            s[f * 9 + rr + 0] = t.x; s[f * 9 + rr + 1] = t.y;
            s[f * 9 + rr + 2] = t.z; s[f * 9 + rr + 3] = t.w;
        }
        __syncthreads();
#pragma unroll
        for (int rr = 0; rr < 8; rr++) {
            int f = threadIdx.x * 2;
            __half2 h = make_half2(__float2half_rn(s[f * 9 + rr]),
                                   __float2half_rn(s[(f + 1) * 9 + rr]));
            *(__half2*)(g_xt + ((size_t)n * 8 + rr) * 512 + f) = h;
        }
    } else if (b < NE + 768) {
        int idx = ((b - NE) * 256 + threadIdx.x) * 4;
        int p = idx >> 18, off = idx & 262143;
        const float* W = (p == 0) ? Wq : (p == 1) ? Wk : Wd;
        float4 t = *(const float4*)(W + off);
        *(__half2*)(g_W + idx)     = make_half2(__float2half_rn(t.x), __float2half_rn(t.y));
        *(__half2*)(g_W + idx + 2) = make_half2(__float2half_rn(t.z), __float2half_rn(t.w));
    } else {
        int i = (b - NE - 768) * 256 + threadIdx.x;
        if (i < 3 * NE) g_ss[i] = 0.f;
        if (i < HEAD * NE) g_rs[i] = 0.f;
    }
}

// ---------------- projection GEMM + fused sum-of-squares --------------------
__global__ __launch_bounds__(128) void proj_tc() {
    extern __shared__ __half dsm[];
    __shared__ float csum[128];
    __half* sA = dsm;
    __half* sB = dsm + STG * ASTRH;
    const int p = blockIdx.z;
    const int m0 = blockIdx.y * 128, c0 = blockIdx.x * 128;

    const int tid = threadIdx.x, lane = tid & 31, wid = tid >> 5;
    const int g8 = lane >> 2, tg = lane & 3;
    const int wm = (wid & 1) * 64, wn = (wid >> 1) * 64;

    if (tid < 128) csum[tid] = 0.f;

    Acc F;
    gemm_main(F, g_W + (size_t)p * HL * FEAT + (size_t)m0 * FEAT,
              g_xt + (size_t)c0 * FEAT, FEAT, sA, sB);

    float sq[8];
#pragma unroll
    for (int nt = 0; nt < 8; nt++) sq[nt] = 0.f;

    if (p < 2) {
        __half* base = g_Y + (size_t)p * HEAD * NE * 512;
#pragma unroll
        for (int mt = 0; mt < 4; mt++)
#pragma unroll
            for (int half = 0; half < 2; half++) {
                int row = m0 + wm + mt * 16 + g8 + half * 8;
                int hh = row >> 6, l = row & 63;
#pragma unroll
                for (int nt = 0; nt < 8; nt++) {
                    int col = c0 + wn + nt * 8 + 2 * tg;
                    int n = col >> 3, r = col & 7;
                    __half h0 = __float2half_rn(F.a[mt][nt][half * 2 + 0]);
                    __half h1 = __float2half_rn(F.a[mt][nt][half * 2 + 1]);
                    float v0 = __half2float(h0), v1 = __half2float(h1);
                    *(__half2*)(base + ((size_t)hh * NE + n) * 512 + l * 8 + r) = make_half2(h0, h1);
                    sq[nt] += v0 * v0 + v1 * v1;
                }
            }
    } else {
        int mb = (c0 >> 3) + (wn >> 3);
#pragma unroll
        for (int mt = 0; mt < 4; mt++)
#pragma unroll
            for (int half = 0; half < 2; half++) {
                int row = m0 + wm + mt * 16 + g8 + half * 8;
                int hh = row >> 6, l = row & 63;
#pragma unroll
                for (int par = 0; par < 2; par++) {
                    __half hv[8];
#pragma unroll
                    for (int nt = 0; nt < 8; nt++) {
                        hv[nt] = __float2half_rn(F.a[mt][nt][half * 2 + par]);
                        float v = __half2float(hv[nt]);
                        sq[nt] += v * v;
                    }
                    int lr = l * 8 + 2 * tg + par;
                    *(uint4*)(g_Yd + ((size_t)hh * 512 + lr) * NE + mb) = *(uint4*)hv;
                }
            }
    }
#pragma unroll
    for (int nt = 0; nt < 8; nt++) {
        float v = sq[nt];
        v += __shfl_down_sync(0xffffffffu, v, 4);
        v += __shfl_down_sync(0xffffffffu, v, 8);
        v += __shfl_down_sync(0xffffffffu, v, 16);
        if (g8 == 0) atomicAdd(&csum[wn + nt * 8 + 2 * tg], v);
    }
    __syncthreads();
    if (tid < 16) {
        float s = 0.f;
#pragma unroll
        for (int j = 0; j < 8; j += 2) s += csum[tid * 8 + j];
        atomicAdd(&g_ss[p * NE + (c0 >> 3) + tid], s);
    }
}

// ---------------- scores GEMM + fused exp/softmax-numerator -----------------
__global__ __launch_bounds__(128) void scores_tc() {
    extern __shared__ __half dsm[];
    __shared__ float rsum[128];
    __half* sA = dsm;
    __half* sB = dsm + STG * ASTRH;
    const int h = blockIdx.z;
    const int m0 = blockIdx.y * 128, n0 = blockIdx.x * 128;

    const int tid = threadIdx.x, lane = tid & 31, wid = tid >> 5;
    const int g8 = lane >> 2, tg = lane & 3;
    const int wm = (wid & 1) * 64, wn = (wid >> 1) * 64;

    if (tid < 128) rsum[tid] = 0.f;

    Acc F;
    gemm_main(F, g_Y + ((size_t)h * NE + m0) * 512,
              g_Y + (((size_t)HEAD + h) * NE + n0) * 512, 512, sA, sB);

    float rk[8][2], rd[8][2];
#pragma unroll
    for (int nt = 0; nt < 8; nt++) {
        int col = n0 + wn + nt * 8 + 2 * tg;
        rk[nt][0] = rsqrtf(g_ss[NE + col]);     rk[nt][1] = rsqrtf(g_ss[NE + col + 1]);
        rd[nt][0] = rsqrtf(g_ss[2 * NE + col]); rd[nt][1] = rsqrtf(g_ss[2 * NE + col + 1]);
    }

#pragma unroll
    for (int mt = 0; mt < 4; mt++)
#pragma unroll
        for (int half = 0; half < 2; half++) {
            int row = m0 + wm + mt * 16 + g8 + half * 8;
            float rq = rsqrtf(g_ss[row]);
            float rs = 0.f;
#pragma unroll
            for (int nt = 0; nt < 8; nt++) {
                int col = n0 + wn + nt * 8 + 2 * tg;
                float e0 = __expf(F.a[mt][nt][half * 2 + 0] * rq * rk[nt][0]);
                float e1 = __expf(F.a[mt][nt][half * 2 + 1] * rq * rk[nt][1]);
                rs += e0 + e1;
                __half2 ph = make_half2(__float2half_rn(e0 * rd[nt][0]),
                                        __float2half_rn(e1 * rd[nt][1]));
                *(__half2*)(g_S + ((size_t)h * NE + row) * NE + col) = ph;
            }
            rs += __shfl_down_sync(0xffffffffu, rs, 1);
            rs += __shfl_down_sync(0xffffffffu, rs, 2);
            if (tg == 0) atomicAdd(&rsum[wm + mt * 16 + g8 + half * 8], rs);
        }
    __syncthreads();
    if (tid < 128) atomicAdd(&g_rs[(size_t)h * NE + m0 + tid], rsum[tid]);
}

// ---------------- combine GEMM, scale rows by 1/rowsum ----------------------
__global__ __launch_bounds__(128) void combine_tc(float* __restrict__ out) {
    extern __shared__ __half dsm[];
    __half* sA = dsm;
    __half* sB = dsm + STG * ASTRH;
    const int h = blockIdx.z;
    const int m0 = blockIdx.y * 128, lr0 = blockIdx.x * 128;

    Acc F;
    gemm_main(F, g_S + ((size_t)h * NE + m0) * NE,
              g_Yd + ((size_t)h * 512 + lr0) * NE, NE, sA, sB);

    const int tid = threadIdx.x, lane = tid & 31, wid = tid >> 5;
    const int g8 = lane >> 2, tg = lane & 3;
    const int wm = (wid & 1) * 64, wn = (wid >> 1) * 64;

#pragma unroll
    for (int mt = 0; mt < 4; mt++)
#pragma unroll
        for (int half = 0; half < 2; half++) {
            int row = m0 + wm + mt * 16 + g8 + half * 8;
            float inv = 1.0f / g_rs[(size_t)h * NE + row];
#pragma unroll
            for (int nt = 0; nt < 8; nt++) {
                int col = lr0 + wn + nt * 8 + 2 * tg;
                float v0 = F.a[mt][nt][half * 2 + 0] * inv;
                float v1 = F.a[mt][nt][half * 2 + 1] * inv;
                *(float2*)(out + (size_t)row * OUTC + h * 512 + col) = make_float2(v0, v1);
            }
        }
}

// ---------------------------------------------------------------------------
extern "C" void kernel_launch(void* const* d_in, const int* in_sizes, int n_in,
                              void* d_out, int out_size) {
    const float* x  = (const float*)d_in[0];
    const float* Wq = (const float*)d_in[1];
    const float* Wk = (const float*)d_in[2];
    const float* Wd = (const float*)d_in[3];
    float* out = (float*)d_out;

    cudaFuncSetAttribute(proj_tc,    cudaFuncAttributeMaxDynamicSharedMemorySize, SMEM_BYTES);
    cudaFuncSetAttribute(scores_tc,  cudaFuncAttributeMaxDynamicSharedMemorySize, SMEM_BYTES);
    cudaFuncSetAttribute(combine_tc, cudaFuncAttributeMaxDynamicSharedMemorySize, SMEM_BYTES);

    prep_all<<<NE + 768 + 64, 256>>>(x, Wq, Wk, Wd);
    proj_tc<<<dim3(NCOL / 128, HL / 128, 3), 128, SMEM_BYTES>>>();
    scores_tc<<<dim3(NE / 128, NE / 128, HEAD), 128, SMEM_BYTES>>>();
    combine_tc<<<dim3(512 / 128, NE / 128, HEAD), 128, SMEM_BYTES>>>(out);
}

// round 12
// speedup vs baseline: 1.1157x; 1.1157x over previous
#include <cuda_runtime.h>
#include <cuda_fp16.h>
#include <math.h>
#include <stdint.h>

#define NE    2048
#define FEAT  512
#define REST  8
#define HEAD  8
#define HL    512
#define NCOL  16384
#define OUTC  (HEAD*512)
#define BKH   64
#define PADH  72
#define STG   3
#define SM128 (3 * (128 + 128) * PADH * 2)   // 110592
#define SM256 (3 * (256 + 128) * PADH * 2)   // 165888

// ---------------- scratch ----------------------------------------------------
__device__ __half g_Y  [(size_t)2 * HEAD * NE * 512];
__device__ __half g_Yd [(size_t)HEAD * 512 * NE];
__device__ __half g_xt [(size_t)NCOL * FEAT];
__device__ __half g_W  [(size_t)3 * HL * FEAT];
__device__ __half g_S  [(size_t)HEAD * NE * NE];
__device__ float  g_ss [3 * NE];
__device__ float  g_rs [(size_t)HEAD * NE];

// ---------------- helpers ----------------------------------------------------
__device__ __forceinline__ uint32_t smem_u32(const void* p) {
    uint32_t a;
    asm("{ .reg .u64 t; cvta.to.shared.u64 t, %1; cvt.u32.u64 %0, t; }" : "=r"(a) : "l"(p));
    return a;
}
__device__ __forceinline__ void mma16(float* c, const uint32_t* a, const uint32_t* b) {
    asm volatile(
        "mma.sync.aligned.m16n8k16.row.col.f32.f16.f16.f32 "
        "{%0,%1,%2,%3}, {%4,%5,%6,%7}, {%8,%9}, {%0,%1,%2,%3};"
        : "+f"(c[0]), "+f"(c[1]), "+f"(c[2]), "+f"(c[3])
        : "r"(a[0]), "r"(a[1]), "r"(a[2]), "r"(a[3]), "r"(b[0]), "r"(b[1]));
}
__device__ __forceinline__ void ldsm4(uint32_t* r, uint32_t addr) {
    asm volatile("ldmatrix.sync.aligned.m8n8.x4.shared.b16 {%0,%1,%2,%3}, [%4];"
                 : "=r"(r[0]), "=r"(r[1]), "=r"(r[2]), "=r"(r[3]) : "r"(addr));
}
__device__ __forceinline__ void cp16(uint32_t dst, const void* src) {
    uint64_t g;
    asm("cvta.to.global.u64 %0, %1;" : "=l"(g) : "l"(src));
    asm volatile("cp.async.cg.shared.global [%0], [%1], 16;" :: "r"(dst), "l"(g));
}

// ROWS x 64-half K-major tile loaded by NT threads
template<int ROWS, int NT>
__device__ __forceinline__ void ld_k(__half* S, const __half* gp, int ldk, int k0, int tid) {
#pragma unroll
    for (int i = 0; i < ROWS * 8 / NT; i++) {
        int idx = tid + i * NT;
        int row = idx >> 3, ch = idx & 7;
        cp16(smem_u32(S + row * PADH + ch * 8), gp + (size_t)row * ldk + k0 + ch * 8);
    }
}

struct Acc { float a[4][8][4]; };

// ------- 3-stage pipeline, fragment double-buffered, AR x 128 CTA tile -------
// AR=128: 128 threads, 4 warps (2m x 2n).  AR=256: 256 threads, 8 warps (4m x 2n).
template<int AR>
__device__ __forceinline__ void gemm_main(Acc& F, const __half* A, const __half* B,
                                          int K, __half* sA, __half* sB) {
    const int NT = (AR == 256) ? 256 : 128;
    const int ASTR_T = AR * PADH, BSTR_T = 128 * PADH;
    const int tid = threadIdx.x;
    const int lane = tid & 31, wid = tid >> 5;
    const int wm = (AR == 256) ? (wid & 3) * 64 : (wid & 1) * 64;
    const int wn = (AR == 256) ? (wid >> 2) * 64 : (wid >> 1) * 64;

    const int offA = (wm + (lane & 7) + ((lane >> 3) & 1) * 8) * PADH + ((lane >> 4) & 1) * 8;
    const int offB = (wn + (lane & 7) + ((lane >> 4) & 1) * 8) * PADH + ((lane >> 3) & 1) * 8;

    const uint32_t sA0 = smem_u32(sA), sB0 = smem_u32(sB);

#pragma unroll
    for (int mt = 0; mt < 4; mt++)
#pragma unroll
        for (int nt = 0; nt < 8; nt++)
#pragma unroll
            for (int j = 0; j < 4; j++) F.a[mt][nt][j] = 0.f;

#pragma unroll
    for (int s = 0; s < STG - 1; s++) {
        ld_k<AR, NT>(sA + s * ASTR_T, A, K, s * BKH, tid);
        ld_k<128, NT>(sB + s * BSTR_T, B, K, s * BKH, tid);
        asm volatile("cp.async.commit_group;" ::: "memory");
    }

    const int KT = K / BKH;
    int ls = STG - 1;
    for (int kt = 0; kt < KT; kt++) {
        asm volatile("cp.async.wait_group %0;" :: "n"(STG - 2) : "memory");
        __syncthreads();
        if (kt + STG - 1 < KT) {
            ld_k<AR, NT>(sA + ls * ASTR_T, A, K, (kt + STG - 1) * BKH, tid);
            ld_k<128, NT>(sB + ls * BSTR_T, B, K, (kt + STG - 1) * BKH, tid);
            ls = (ls + 1 == STG) ? 0 : ls + 1;
        }
        asm volatile("cp.async.commit_group;" ::: "memory");

        int buf = kt % STG;
        const uint32_t aB = sA0 + (buf * ASTR_T + offA) * 2;
        const uint32_t bB = sB0 + (buf * BSTR_T + offB) * 2;

        uint32_t af[2][4][4], bf[2][4][4];
#pragma unroll
        for (int mt = 0; mt < 4; mt++) ldsm4(af[0][mt], aB + (mt * 16 * PADH) * 2);
#pragma unroll
        for (int np = 0; np < 4; np++) ldsm4(bf[0][np], bB + (np * 16 * PADH) * 2);

#pragma unroll
        for (int ks = 0; ks < 4; ks++) {
            int cur = ks & 1, nxt = cur ^ 1;
            if (ks < 3) {
#pragma unroll
                for (int mt = 0; mt < 4; mt++)
                    ldsm4(af[nxt][mt], aB + (mt * 16 * PADH + 16 * (ks + 1)) * 2);
#pragma unroll
                for (int np = 0; np < 4; np++)
                    ldsm4(bf[nxt][np], bB + (np * 16 * PADH + 16 * (ks + 1)) * 2);
            }
#pragma unroll
            for (int mt = 0; mt < 4; mt++)
#pragma unroll
                for (int np = 0; np < 4; np++) {
                    mma16(F.a[mt][2 * np + 0], af[cur][mt], &bf[cur][np][0]);
                    mma16(F.a[mt][2 * np + 1], af[cur][mt], &bf[cur][np][2]);
                }
        }
    }
    __syncthreads();
}

// ---------------- fused prep ------------------------------------------------
__global__ __launch_bounds__(256) void prep_all(const float* __restrict__ x,
                                                const float* __restrict__ Wq,
                                                const float* __restrict__ Wk,
                                                const float* __restrict__ Wd) {
    int b = blockIdx.x;
    if (b < NE) {
        __shared__ float s[512 * 9];
        const int n = b, tid = threadIdx.x;
        const float* src = x + (size_t)n * 4096;
#pragma unroll
        for (int i = 0; i < 4; i++) {
            int v = (tid + i * 256) * 4;
            float4 t = *(const float4*)(src + v);
            int f = v >> 3, rr = v & 7;
            s[f * 9 + rr + 0] = t.x; s[f * 9 + rr + 1] = t.y;
            s[f * 9 + rr + 2] = t.z; s[f * 9 + rr + 3] = t.w;
        }
        __syncthreads();
#pragma unroll
        for (int rr = 0; rr < 8; rr++) {
            int f = threadIdx.x * 2;
            __half2 h = make_half2(__float2half_rn(s[f * 9 + rr]),
                                   __float2half_rn(s[(f + 1) * 9 + rr]));
            *(__half2*)(g_xt + ((size_t)n * 8 + rr) * 512 + f) = h;
        }
    } else if (b < NE + 768) {
        int idx = ((b - NE) * 256 + threadIdx.x) * 4;
        int p = idx >> 18, off = idx & 262143;
        const float* W = (p == 0) ? Wq : (p == 1) ? Wk : Wd;
        float4 t = *(const float4*)(W + off);
        *(__half2*)(g_W + idx)     = make_half2(__float2half_rn(t.x), __float2half_rn(t.y));
        *(__half2*)(g_W + idx + 2) = make_half2(__float2half_rn(t.z), __float2half_rn(t.w));
    } else {
        int i = (b - NE - 768) * 256 + threadIdx.x;
        if (i < 3 * NE) g_ss[i] = 0.f;
        if (i < HEAD * NE) g_rs[i] = 0.f;
    }
}

// ---------------- projection GEMM + fused sum-of-squares (128-tile) ---------
__global__ __launch_bounds__(128) void proj_tc() {
    extern __shared__ __half dsm[];
    __shared__ float csum[128];
    __half* sA = dsm;
    __half* sB = dsm + STG * 128 * PADH;
    const int p = blockIdx.z;
    const int m0 = blockIdx.y * 128, c0 = blockIdx.x * 128;

    const int tid = threadIdx.x, lane = tid & 31, wid = tid >> 5;
    const int g8 = lane >> 2, tg = lane & 3;
    const int wm = (wid & 1) * 64, wn = (wid >> 1) * 64;

    csum[tid] = 0.f;

    Acc F;
    gemm_main<128>(F, g_W + (size_t)p * HL * FEAT + (size_t)m0 * FEAT,
                   g_xt + (size_t)c0 * FEAT, FEAT, sA, sB);

    float sq[8];
#pragma unroll
    for (int nt = 0; nt < 8; nt++) sq[nt] = 0.f;

    if (p < 2) {
        __half* base = g_Y + (size_t)p * HEAD * NE * 512;
#pragma unroll
        for (int mt = 0; mt < 4; mt++)
#pragma unroll
            for (int half = 0; half < 2; half++) {
                int row = m0 + wm + mt * 16 + g8 + half * 8;
                int hh = row >> 6, l = row & 63;
#pragma unroll
                for (int nt = 0; nt < 8; nt++) {
                    int col = c0 + wn + nt * 8 + 2 * tg;
                    int n = col >> 3, r = col & 7;
                    __half h0 = __float2half_rn(F.a[mt][nt][half * 2 + 0]);
                    __half h1 = __float2half_rn(F.a[mt][nt][half * 2 + 1]);
                    float v0 = __half2float(h0), v1 = __half2float(h1);
                    *(__half2*)(base + ((size_t)hh * NE + n) * 512 + l * 8 + r) = make_half2(h0, h1);
                    sq[nt] += v0 * v0 + v1 * v1;
                }
            }
    } else {
        int mb = (c0 >> 3) + (wn >> 3);
#pragma unroll
        for (int mt = 0; mt < 4; mt++)
#pragma unroll
            for (int half = 0; half < 2; half++) {
                int row = m0 + wm + mt * 16 + g8 + half * 8;
                int hh = row >> 6, l = row & 63;
#pragma unroll
                for (int par = 0; par < 2; par++) {
                    __half hv[8];
#pragma unroll
                    for (int nt = 0; nt < 8; nt++) {
                        hv[nt] = __float2half_rn(F.a[mt][nt][half * 2 + par]);
                        float v = __half2float(hv[nt]);
                        sq[nt] += v * v;
                    }
                    int lr = l * 8 + 2 * tg + par;
                    *(uint4*)(g_Yd + ((size_t)hh * 512 + lr) * NE + mb) = *(uint4*)hv;
                }
            }
    }
#pragma unroll
    for (int nt = 0; nt < 8; nt++) {
        float v = sq[nt];
        v += __shfl_down_sync(0xffffffffu, v, 4);
        v += __shfl_down_sync(0xffffffffu, v, 8);
        v += __shfl_down_sync(0xffffffffu, v, 16);
        if (g8 == 0) atomicAdd(&csum[wn + nt * 8 + 2 * tg], v);
    }
    __syncthreads();
    if (tid < 16) {
        float s = 0.f;
#pragma unroll
        for (int j = 0; j < 8; j += 2) s += csum[tid * 8 + j];
        atomicAdd(&g_ss[p * NE + (c0 >> 3) + tid], s);
    }
}

// ---------------- scores GEMM (256x128 tile) + fused exp --------------------
__global__ __launch_bounds__(256) void scores_tc() {
    extern __shared__ __half dsm[];
    __shared__ float rsum[256];
    __half* sA = dsm;
    __half* sB = dsm + STG * 256 * PADH;
    const int h = blockIdx.z;
    const int m0 = blockIdx.y * 256, n0 = blockIdx.x * 128;

    const int tid = threadIdx.x, lane = tid & 31, wid = tid >> 5;
    const int g8 = lane >> 2, tg = lane & 3;
    const int wm = (wid & 3) * 64, wn = (wid >> 2) * 64;

    rsum[tid] = 0.f;

    Acc F;
    gemm_main<256>(F, g_Y + ((size_t)h * NE + m0) * 512,
                   g_Y + (((size_t)HEAD + h) * NE + n0) * 512, 512, sA, sB);

    float rk[8][2], rd[8][2];
#pragma unroll
    for (int nt = 0; nt < 8; nt++) {
        int col = n0 + wn + nt * 8 + 2 * tg;
        rk[nt][0] = rsqrtf(g_ss[NE + col]);     rk[nt][1] = rsqrtf(g_ss[NE + col + 1]);
        rd[nt][0] = rsqrtf(g_ss[2 * NE + col]); rd[nt][1] = rsqrtf(g_ss[2 * NE + col + 1]);
    }

#pragma unroll
    for (int mt = 0; mt < 4; mt++)
#pragma unroll
        for (int half = 0; half < 2; half++) {
            int row = m0 + wm + mt * 16 + g8 + half * 8;
            float rq = rsqrtf(g_ss[row]);
            float rs = 0.f;
#pragma unroll
            for (int nt = 0; nt < 8; nt++) {
                int col = n0 + wn + nt * 8 + 2 * tg;
                float e0 = __expf(F.a[mt][nt][half * 2 + 0] * rq * rk[nt][0]);
                float e1 = __expf(F.a[mt][nt][half * 2 + 1] * rq * rk[nt][1]);
                rs += e0 + e1;
                __half2 ph = make_half2(__float2half_rn(e0 * rd[nt][0]),
                                        __float2half_rn(e1 * rd[nt][1]));
                *(__half2*)(g_S + ((size_t)h * NE + row) * NE + col) = ph;
            }
            rs += __shfl_down_sync(0xffffffffu, rs, 1);
            rs += __shfl_down_sync(0xffffffffu, rs, 2);
            if (tg == 0) atomicAdd(&rsum[wm + mt * 16 + g8 + half * 8], rs);
        }
    __syncthreads();
    atomicAdd(&g_rs[(size_t)h * NE + m0 + tid], rsum[tid]);
}

// ---------------- combine GEMM (128-tile), scale by 1/rowsum ----------------
__global__ __launch_bounds__(128) void combine_tc(float* __restrict__ out) {
    extern __shared__ __half dsm[];
    __half* sA = dsm;
    __half* sB = dsm + STG * 128 * PADH;
    const int h = blockIdx.z;
    const int m0 = blockIdx.y * 128, lr0 = blockIdx.x * 128;

    Acc F;
    gemm_main<128>(F, g_S + ((size_t)h * NE + m0) * NE,
                   g_Yd + ((size_t)h * 512 + lr0) * NE, NE, sA, sB);

    const int tid = threadIdx.x, lane = tid & 31, wid = tid >> 5;
    const int g8 = lane >> 2, tg = lane & 3;
    const int wm = (wid & 1) * 64, wn = (wid >> 1) * 64;

#pragma unroll
    for (int mt = 0; mt < 4; mt++)
#pragma unroll
        for (int half = 0; half < 2; half++) {
            int row = m0 + wm + mt * 16 + g8 + half * 8;
            float inv = 1.0f / g_rs[(size_t)h * NE + row];
#pragma unroll
            for (int nt = 0; nt < 8; nt++) {
                int col = lr0 + wn + nt * 8 + 2 * tg;
                float v0 = F.a[mt][nt][half * 2 + 0] * inv;
                float v1 = F.a[mt][nt][half * 2 + 1] * inv;
                *(float2*)(out + (size_t)row * OUTC + h * 512 + col) = make_float2(v0, v1);
            }
        }
}

// ---------------------------------------------------------------------------
extern "C" void kernel_launch(void* const* d_in, const int* in_sizes, int n_in,
                              void* d_out, int out_size) {
    const float* x  = (const float*)d_in[0];
    const float* Wq = (const float*)d_in[1];
    const float* Wk = (const float*)d_in[2];
    const float* Wd = (const float*)d_in[3];
    float* out = (float*)d_out;

    cudaFuncSetAttribute(proj_tc,    cudaFuncAttributeMaxDynamicSharedMemorySize, SM128);
    cudaFuncSetAttribute(scores_tc,  cudaFuncAttributeMaxDynamicSharedMemorySize, SM256);
    cudaFuncSetAttribute(combine_tc, cudaFuncAttributeMaxDynamicSharedMemorySize, SM128);

    prep_all<<<NE + 768 + 64, 256>>>(x, Wq, Wk, Wd);
    proj_tc<<<dim3(NCOL / 128, HL / 128, 3), 128, SM128>>>();
    scores_tc<<<dim3(NE / 128, NE / 256, HEAD), 256, SM256>>>();
    combine_tc<<<dim3(512 / 128, NE / 128, HEAD), 128, SM128>>>(out);
}